// round 1
// baseline (speedup 1.0000x reference)
#include <cuda_runtime.h>
#include <math.h>

// Problem constants (from reference setup_inputs)
#define BB      4
#define NPTS    4096
#define MPTS    4096
#define TSPLIT  4
#define CHUNK   (MPTS / TSPLIT)   // 1024 targets per chunk
#define SBLK    (NPTS / 256)      // 16 source blocks per batch
#define ICP_STEPS 16
#define ICP_TOL   1e-6

// ---------------------------------------------------------------------------
// Device-global scratch (no allocations allowed)
// ---------------------------------------------------------------------------
__device__ float               g_temp[BB * NPTS * 3];        // "temporal" cloud
__device__ unsigned long long  g_cand[TSPLIT][BB * NPTS];    // packed (mono(s)<<16 | j)
__device__ float               g_part[BB][SBLK][16];         // per-block partial sums
__device__ float               g_Rt[BB][12];                 // current step transform [R(9), t(3)]
__device__ double              g_errlast[BB];
__device__ int                 g_done;

// ---------------------------------------------------------------------------
// Shared transform helper — must be bit-identical between kernels
// ---------------------------------------------------------------------------
__device__ __forceinline__ void xform(const float* __restrict__ Mtx,
                                      float px, float py, float pz,
                                      float& qx, float& qy, float& qz) {
    qx = fmaf(Mtx[0], px, fmaf(Mtx[1], py, fmaf(Mtx[2], pz, Mtx[9])));
    qy = fmaf(Mtx[3], px, fmaf(Mtx[4], py, fmaf(Mtx[5], pz, Mtx[10])));
    qz = fmaf(Mtx[6], px, fmaf(Mtx[7], py, fmaf(Mtx[8], pz, Mtx[11])));
}

// monotone uint mapping of float: preserves < ordering
__device__ __forceinline__ unsigned int fmono(float f) {
    unsigned int b = __float_as_uint(f);
    return (b & 0x80000000u) ? ~b : (b | 0x80000000u);
}
__device__ __forceinline__ float fmono_inv(unsigned int m) {
    unsigned int b = (m & 0x80000000u) ? (m ^ 0x80000000u) : ~m;
    return __uint_as_float(b);
}

// ---------------------------------------------------------------------------
// Init: temporal = source; transform = identity; flags reset
// ---------------------------------------------------------------------------
__global__ void init_kernel(const float* __restrict__ src) {
    int i = blockIdx.x * blockDim.x + threadIdx.x;
    if (i < BB * NPTS * 3) g_temp[i] = src[i];
    if (blockIdx.x == 0) {
        if (threadIdx.x < BB * 12) {
            int k = threadIdx.x % 12;
            g_Rt[threadIdx.x / 12][k] = (k == 0 || k == 4 || k == 8) ? 1.f : 0.f;
        }
        if (threadIdx.x < BB) g_errlast[threadIdx.x] = 0.0;
        if (threadIdx.x == 0) g_done = 0;
    }
}

// ---------------------------------------------------------------------------
// NN kernel: applies pending transform (read-only), scans one target chunk,
// writes packed per-(source,chunk) best candidate.
// grid (SBLK, TSPLIT, BB), block 256
// ---------------------------------------------------------------------------
__global__ void nn_kernel(const float* __restrict__ target) {
    __shared__ float4 tg[CHUNK];
    const int b  = blockIdx.z;
    const int cy = blockIdx.y;

    // stage target chunk into shared as (x, y, z, |t|^2)
    const float* T = target + (size_t)(b * MPTS + cy * CHUNK) * 3;
    for (int k = threadIdx.x; k < CHUNK; k += blockDim.x) {
        float x = T[3 * k], y = T[3 * k + 1], z = T[3 * k + 2];
        tg[k] = make_float4(x, y, z, fmaf(x, x, fmaf(y, y, z * z)));
    }

    const int n   = blockIdx.x * blockDim.x + threadIdx.x;
    const int idx = b * NPTS + n;
    float px = g_temp[3 * idx], py = g_temp[3 * idx + 1], pz = g_temp[3 * idx + 2];
    float wx, wy, wz;
    xform(g_Rt[b], px, py, pz, wx, wy, wz);
    const float ax = -2.f * wx, ay = -2.f * wy, az = -2.f * wz;

    __syncthreads();

    float smin = 3.4e38f;
    int   jb   = 0;
#pragma unroll 8
    for (int j = 0; j < CHUNK; ++j) {
        float4 q = tg[j];
        float  s = fmaf(ax, q.x, fmaf(ay, q.y, fmaf(az, q.z, q.w)));
        if (s < smin) { smin = s; jb = j; }   // strict < : first index wins ties
    }

    unsigned long long key =
        ((unsigned long long)fmono(smin) << 16) | (unsigned)(cy * CHUNK + jb);
    g_cand[cy][idx] = key;
}

// ---------------------------------------------------------------------------
// Deterministic 16-way block reduction -> g_part
// ---------------------------------------------------------------------------
__device__ __forceinline__ void block_reduce16(const float v[16], int b, int blk) {
    __shared__ float wsum[8][16];
    const int lane = threadIdx.x & 31, wid = threadIdx.x >> 5;
#pragma unroll
    for (int q = 0; q < 16; ++q) {
        float r = v[q];
#pragma unroll
        for (int o = 16; o > 0; o >>= 1) r += __shfl_down_sync(0xffffffffu, r, o);
        if (lane == 0) wsum[wid][q] = r;
    }
    __syncthreads();
    if (threadIdx.x < 16) {
        float acc = 0.f;
#pragma unroll
        for (int w = 0; w < 8; ++w) acc += wsum[w][threadIdx.x];
        g_part[b][blk][threadIdx.x] = acc;
    }
}

// ---------------------------------------------------------------------------
// Moments kernel: combine candidates, apply+write-back transform, accumulate
// {sum p, sum tnn, sum p (x) tnn, sum sqrt(d2)} as 16 block partials.
// grid (SBLK, 1, BB), block 256
// ---------------------------------------------------------------------------
__global__ void mom_kernel(const float* __restrict__ target) {
    const int b   = blockIdx.z;
    const int n   = blockIdx.x * blockDim.x + threadIdx.x;
    const int idx = b * NPTS + n;

    unsigned long long key = g_cand[0][idx];
    key = min(key, g_cand[1][idx]);
    key = min(key, g_cand[2][idx]);
    key = min(key, g_cand[3][idx]);
    const unsigned j = (unsigned)(key & 0xFFFFu);
    const float    s = fmono_inv((unsigned int)(key >> 16));

    float px = g_temp[3 * idx], py = g_temp[3 * idx + 1], pz = g_temp[3 * idx + 2];
    float wx, wy, wz;
    xform(g_Rt[b], px, py, pz, wx, wy, wz);   // identical arithmetic to nn_kernel
    g_temp[3 * idx] = wx; g_temp[3 * idx + 1] = wy; g_temp[3 * idx + 2] = wz;

    const float a2 = fmaf(wx, wx, fmaf(wy, wy, wz * wz));
    const float d2 = fmaxf(s + a2, 0.f);
    const float ec = sqrtf(d2);

    const float* tp = target + (size_t)(b * MPTS + j) * 3;
    const float tx = tp[0], ty = tp[1], tz = tp[2];

    const float v[16] = { wx, wy, wz, tx, ty, tz,
                          wx * tx, wx * ty, wx * tz,
                          wy * tx, wy * ty, wy * tz,
                          wz * tx, wz * ty, wz * tz, ec };
    block_reduce16(v, b, blockIdx.x);
}

// Final moments: src = original source, tgt = transform(temporal) (no writeback)
__global__ void fmom_kernel(const float* __restrict__ source) {
    const int b   = blockIdx.z;
    const int n   = blockIdx.x * blockDim.x + threadIdx.x;
    const int idx = b * NPTS + n;

    float px = g_temp[3 * idx], py = g_temp[3 * idx + 1], pz = g_temp[3 * idx + 2];
    float wx, wy, wz;
    xform(g_Rt[b], px, py, pz, wx, wy, wz);

    const float sx = source[3 * idx], sy = source[3 * idx + 1], sz = source[3 * idx + 2];

    const float v[16] = { sx, sy, sz, wx, wy, wz,
                          sx * wx, sx * wy, sx * wz,
                          sy * wx, sy * wy, sy * wz,
                          sz * wx, sz * wy, sz * wz, 0.f };
    block_reduce16(v, b, blockIdx.x);
}

// ---------------------------------------------------------------------------
// Kabsch from accumulated sums (fp64). Returns Rt[12] = [R row-major, t].
// R = V diag(1,1,d) U^T with H = U S V^T, identical optimum to reference.
// ---------------------------------------------------------------------------
__device__ void kabsch_sums(const double* S, double* Rt) {
    const double invN = 1.0 / (double)NPTS;
    double cs[3] = { S[0] * invN, S[1] * invN, S[2] * invN };
    double ct[3] = { S[3] * invN, S[4] * invN, S[5] * invN };

    double H[3][3];
    for (int i = 0; i < 3; ++i)
        for (int j = 0; j < 3; ++j)
            H[i][j] = S[6 + 3 * i + j] - (double)NPTS * cs[i] * ct[j];

    // A = H^T H (symmetric PSD)
    double A[3][3];
    for (int i = 0; i < 3; ++i)
        for (int j = 0; j < 3; ++j)
            A[i][j] = H[0][i] * H[0][j] + H[1][i] * H[1][j] + H[2][i] * H[2][j];

    double V[3][3] = { {1,0,0},{0,1,0},{0,0,1} };
    for (int sweep = 0; sweep < 12; ++sweep) {
        for (int pq = 0; pq < 3; ++pq) {
            const int p = (pq == 2) ? 1 : 0;
            const int q = (pq == 0) ? 1 : 2;
            const double apq = A[p][q];
            if (fabs(apq) <= 0.0) continue;
            const double theta = (A[q][q] - A[p][p]) / (2.0 * apq);
            const double tt = ((theta >= 0.0) ? 1.0 : -1.0) /
                              (fabs(theta) + sqrt(theta * theta + 1.0));
            const double c = 1.0 / sqrt(tt * tt + 1.0);
            const double s = tt * c;
            for (int k = 0; k < 3; ++k) { double a1 = A[p][k], a2 = A[q][k];
                A[p][k] = c * a1 - s * a2; A[q][k] = s * a1 + c * a2; }
            for (int k = 0; k < 3; ++k) { double a1 = A[k][p], a2 = A[k][q];
                A[k][p] = c * a1 - s * a2; A[k][q] = s * a1 + c * a2; }
            for (int k = 0; k < 3; ++k) { double v1 = V[k][p], v2 = V[k][q];
                V[k][p] = c * v1 - s * v2; V[k][q] = s * v1 + c * v2; }
        }
    }

    // sort eigenpairs descending
    int id[3] = { 0, 1, 2 };
    double w[3] = { A[0][0], A[1][1], A[2][2] };
    if (w[id[0]] < w[id[1]]) { int t0 = id[0]; id[0] = id[1]; id[1] = t0; }
    if (w[id[0]] < w[id[2]]) { int t0 = id[0]; id[0] = id[2]; id[2] = t0; }
    if (w[id[1]] < w[id[2]]) { int t0 = id[1]; id[1] = id[2]; id[2] = t0; }

    double v1[3], v2[3], v3[3];
    for (int k = 0; k < 3; ++k) { v1[k] = V[k][id[0]]; v2[k] = V[k][id[1]]; v3[k] = V[k][id[2]]; }

    double u1[3], u2[3], u3[3];
    for (int i = 0; i < 3; ++i) u1[i] = H[i][0] * v1[0] + H[i][1] * v1[1] + H[i][2] * v1[2];
    {
        double n1 = sqrt(u1[0]*u1[0] + u1[1]*u1[1] + u1[2]*u1[2]);
        double r = (n1 > 0.0) ? 1.0 / n1 : 0.0;
        u1[0] *= r; u1[1] *= r; u1[2] *= r;
    }
    for (int i = 0; i < 3; ++i) u2[i] = H[i][0] * v2[0] + H[i][1] * v2[1] + H[i][2] * v2[2];
    {
        double pr = u1[0]*u2[0] + u1[1]*u2[1] + u1[2]*u2[2];
        u2[0] -= pr * u1[0]; u2[1] -= pr * u1[1]; u2[2] -= pr * u1[2];
        double n2 = sqrt(u2[0]*u2[0] + u2[1]*u2[1] + u2[2]*u2[2]);
        double r = (n2 > 0.0) ? 1.0 / n2 : 0.0;
        u2[0] *= r; u2[1] *= r; u2[2] *= r;
    }
    u3[0] = u1[1]*u2[2] - u1[2]*u2[1];
    u3[1] = u1[2]*u2[0] - u1[0]*u2[2];
    u3[2] = u1[0]*u2[1] - u1[1]*u2[0];

    // d = det(V_sorted) (det(U)=+1 by construction)
    const double d =
        v1[0] * (v2[1]*v3[2] - v2[2]*v3[1]) -
        v1[1] * (v2[0]*v3[2] - v2[2]*v3[0]) +
        v1[2] * (v2[0]*v3[1] - v2[1]*v3[0]);

    for (int i = 0; i < 3; ++i)
        for (int j = 0; j < 3; ++j)
            Rt[3 * i + j] = v1[i]*u1[j] + v2[i]*u2[j] + d * v3[i]*u3[j];
    for (int i = 0; i < 3; ++i)
        Rt[9 + i] = ct[i] - (Rt[3*i]*cs[0] + Rt[3*i+1]*cs[1] + Rt[3*i+2]*cs[2]);
}

// ---------------------------------------------------------------------------
// Finalize one ICP step: sum partials, kabsch, convergence, publish transform
// 1 block, 128 threads
// ---------------------------------------------------------------------------
__global__ void fin_kernel() {
    __shared__ double sums[BB][16];
    __shared__ double Rsh[BB][12];
    __shared__ double errsh[BB];
    __shared__ int    convf[BB];
    __shared__ int    doneflag;

    const int tid = threadIdx.x;
    if (tid < BB * 16) {
        const int b = tid >> 4, q = tid & 15;
        double acc = 0.0;
        for (int blk = 0; blk < SBLK; ++blk) acc += (double)g_part[b][blk][q];
        sums[b][q] = acc;
    }
    __syncthreads();

    if (tid < BB) {
        const int b = tid;
        const double errnew = sums[b][15] / (double)NPTS;
        errsh[b] = errnew;
        convf[b] = (fabs(errnew - g_errlast[b]) < ICP_TOL) ? 1 : 0;
        kabsch_sums(sums[b], Rsh[b]);
    }
    __syncthreads();

    if (tid == 0) {
        const int all = convf[0] & convf[1] & convf[2] & convf[3];
        doneflag = g_done | all;
        g_done = doneflag;
    }
    __syncthreads();

    if (tid < BB) {
        const int b = tid;
        if (!doneflag) {
            g_errlast[b] = errsh[b];
            for (int k = 0; k < 12; ++k) g_Rt[b][k] = (float)Rsh[b][k];
        } else {
            for (int k = 0; k < 12; ++k)
                g_Rt[b][k] = (k == 0 || k == 4 || k == 8) ? 1.f : 0.f;
        }
    }
}

// Final: kabsch(source, temporal_final) -> d_out [B,3,4]
__global__ void ffin_kernel(float* __restrict__ out) {
    __shared__ double sums[BB][16];
    __shared__ double Rsh[BB][12];

    const int tid = threadIdx.x;
    if (tid < BB * 16) {
        const int b = tid >> 4, q = tid & 15;
        double acc = 0.0;
        for (int blk = 0; blk < SBLK; ++blk) acc += (double)g_part[b][blk][q];
        sums[b][q] = acc;
    }
    __syncthreads();
    if (tid < BB) kabsch_sums(sums[tid], Rsh[tid]);
    __syncthreads();

    if (tid < BB * 12) {
        const int b = tid / 12, k = tid % 12;
        const int i = k / 4, j = k % 4;   // wait: k in [0,12): map to [3][4]
        float val;
        if (j < 3) val = (float)Rsh[b][3 * i + j];
        else       val = (float)Rsh[b][9 + i];
        out[b * 12 + i * 4 + j] = val;
    }
}

// ---------------------------------------------------------------------------
extern "C" void kernel_launch(void* const* d_in, const int* in_sizes, int n_in,
                              void* d_out, int out_size) {
    const float* source = (const float*)d_in[0];
    const float* target = (const float*)d_in[1];
    float*       out    = (float*)d_out;

    init_kernel<<<(BB * NPTS * 3 + 255) / 256, 256>>>(source);

    for (int k = 0; k < ICP_STEPS; ++k) {
        nn_kernel<<<dim3(SBLK, TSPLIT, BB), 256>>>(target);
        mom_kernel<<<dim3(SBLK, 1, BB), 256>>>(target);
        fin_kernel<<<1, 128>>>();
    }

    fmom_kernel<<<dim3(SBLK, 1, BB), 256>>>(source);
    ffin_kernel<<<1, 128>>>(out);
}

// round 2
// speedup vs baseline: 4.4342x; 4.4342x over previous
#include <cuda_runtime.h>
#include <math.h>

// Problem constants (from reference setup_inputs)
#define BB      4
#define NPTS    4096
#define MPTS    4096
#define TSPLIT  4
#define CHUNK   (MPTS / TSPLIT)   // 1024 targets per chunk
#define SBLK    (NPTS / 256)      // 16 source blocks per batch
#define ICP_STEPS 16
#define ICP_TOL   1e-6

// ---------------------------------------------------------------------------
// Device-global scratch (no allocations allowed)
// ---------------------------------------------------------------------------
__device__ float               g_temp[BB * NPTS * 3];        // "temporal" cloud
__device__ unsigned long long  g_cand[TSPLIT][BB * NPTS];    // packed (mono(s)<<16 | j)
__device__ float               g_part[BB][SBLK][16];         // per-block partial sums
__device__ float               g_Rt[BB][12];                 // current step transform [R(9), t(3)]
__device__ double              g_errlast[BB];
__device__ int                 g_done;

// ---------------------------------------------------------------------------
// Shared transform helper — must be bit-identical between kernels
// ---------------------------------------------------------------------------
__device__ __forceinline__ void xform(const float* __restrict__ Mtx,
                                      float px, float py, float pz,
                                      float& qx, float& qy, float& qz) {
    qx = fmaf(Mtx[0], px, fmaf(Mtx[1], py, fmaf(Mtx[2], pz, Mtx[9])));
    qy = fmaf(Mtx[3], px, fmaf(Mtx[4], py, fmaf(Mtx[5], pz, Mtx[10])));
    qz = fmaf(Mtx[6], px, fmaf(Mtx[7], py, fmaf(Mtx[8], pz, Mtx[11])));
}

// monotone uint mapping of float: preserves < ordering
__device__ __forceinline__ unsigned int fmono(float f) {
    unsigned int b = __float_as_uint(f);
    return (b & 0x80000000u) ? ~b : (b | 0x80000000u);
}
__device__ __forceinline__ float fmono_inv(unsigned int m) {
    unsigned int b = (m & 0x80000000u) ? (m ^ 0x80000000u) : ~m;
    return __uint_as_float(b);
}

// ---------------------------------------------------------------------------
// Init: temporal = source; transform = identity; flags reset
// ---------------------------------------------------------------------------
__global__ void init_kernel(const float* __restrict__ src) {
    int i = blockIdx.x * blockDim.x + threadIdx.x;
    if (i < BB * NPTS * 3) g_temp[i] = src[i];
    if (blockIdx.x == 0) {
        if (threadIdx.x < BB * 12) {
            int k = threadIdx.x % 12;
            g_Rt[threadIdx.x / 12][k] = (k == 0 || k == 4 || k == 8) ? 1.f : 0.f;
        }
        if (threadIdx.x < BB) g_errlast[threadIdx.x] = 0.0;
        if (threadIdx.x == 0) g_done = 0;
    }
}

// ---------------------------------------------------------------------------
// NN kernel: applies pending transform (read-only), scans one target chunk,
// writes packed per-(source,chunk) best candidate.
// grid (SBLK, TSPLIT, BB), block 256
// ---------------------------------------------------------------------------
__global__ void nn_kernel(const float* __restrict__ target) {
    __shared__ float4 tg[CHUNK];
    const int b  = blockIdx.z;
    const int cy = blockIdx.y;

    // stage target chunk into shared as (x, y, z, |t|^2)
    const float* T = target + (size_t)(b * MPTS + cy * CHUNK) * 3;
    for (int k = threadIdx.x; k < CHUNK; k += blockDim.x) {
        float x = T[3 * k], y = T[3 * k + 1], z = T[3 * k + 2];
        tg[k] = make_float4(x, y, z, fmaf(x, x, fmaf(y, y, z * z)));
    }

    const int n   = blockIdx.x * blockDim.x + threadIdx.x;
    const int idx = b * NPTS + n;
    float px = g_temp[3 * idx], py = g_temp[3 * idx + 1], pz = g_temp[3 * idx + 2];
    float wx, wy, wz;
    xform(g_Rt[b], px, py, pz, wx, wy, wz);
    const float ax = -2.f * wx, ay = -2.f * wy, az = -2.f * wz;

    __syncthreads();

    float smin = 3.4e38f;
    int   jb   = 0;
#pragma unroll 8
    for (int j = 0; j < CHUNK; ++j) {
        float4 q = tg[j];
        float  s = fmaf(ax, q.x, fmaf(ay, q.y, fmaf(az, q.z, q.w)));
        if (s < smin) { smin = s; jb = j; }   // strict < : first index wins ties
    }

    unsigned long long key =
        ((unsigned long long)fmono(smin) << 16) | (unsigned)(cy * CHUNK + jb);
    g_cand[cy][idx] = key;
}

// ---------------------------------------------------------------------------
// Deterministic 16-way block reduction -> g_part
// ---------------------------------------------------------------------------
__device__ __forceinline__ void block_reduce16(const float v[16], int b, int blk) {
    __shared__ float wsum[8][16];
    const int lane = threadIdx.x & 31, wid = threadIdx.x >> 5;
#pragma unroll
    for (int q = 0; q < 16; ++q) {
        float r = v[q];
#pragma unroll
        for (int o = 16; o > 0; o >>= 1) r += __shfl_down_sync(0xffffffffu, r, o);
        if (lane == 0) wsum[wid][q] = r;
    }
    __syncthreads();
    if (threadIdx.x < 16) {
        float acc = 0.f;
#pragma unroll
        for (int w = 0; w < 8; ++w) acc += wsum[w][threadIdx.x];
        g_part[b][blk][threadIdx.x] = acc;
    }
}

// ---------------------------------------------------------------------------
// Moments kernel: combine candidates, apply+write-back transform, accumulate
// {sum p, sum tnn, sum p (x) tnn, sum sqrt(d2)} as 16 block partials.
// grid (SBLK, 1, BB), block 256
// ---------------------------------------------------------------------------
__global__ void mom_kernel(const float* __restrict__ target) {
    const int b   = blockIdx.z;
    const int n   = blockIdx.x * blockDim.x + threadIdx.x;
    const int idx = b * NPTS + n;

    unsigned long long key = g_cand[0][idx];
    key = min(key, g_cand[1][idx]);
    key = min(key, g_cand[2][idx]);
    key = min(key, g_cand[3][idx]);
    const unsigned j = (unsigned)(key & 0xFFFFu);
    const float    s = fmono_inv((unsigned int)(key >> 16));

    float px = g_temp[3 * idx], py = g_temp[3 * idx + 1], pz = g_temp[3 * idx + 2];
    float wx, wy, wz;
    xform(g_Rt[b], px, py, pz, wx, wy, wz);   // identical arithmetic to nn_kernel
    g_temp[3 * idx] = wx; g_temp[3 * idx + 1] = wy; g_temp[3 * idx + 2] = wz;

    const float a2 = fmaf(wx, wx, fmaf(wy, wy, wz * wz));
    const float d2 = fmaxf(s + a2, 0.f);
    const float ec = sqrtf(d2);

    const float* tp = target + (size_t)(b * MPTS + j) * 3;
    const float tx = tp[0], ty = tp[1], tz = tp[2];

    const float v[16] = { wx, wy, wz, tx, ty, tz,
                          wx * tx, wx * ty, wx * tz,
                          wy * tx, wy * ty, wy * tz,
                          wz * tx, wz * ty, wz * tz, ec };
    block_reduce16(v, b, blockIdx.x);
}

// Final moments: src = original source, tgt = transform(temporal) (no writeback)
__global__ void fmom_kernel(const float* __restrict__ source) {
    const int b   = blockIdx.z;
    const int n   = blockIdx.x * blockDim.x + threadIdx.x;
    const int idx = b * NPTS + n;

    float px = g_temp[3 * idx], py = g_temp[3 * idx + 1], pz = g_temp[3 * idx + 2];
    float wx, wy, wz;
    xform(g_Rt[b], px, py, pz, wx, wy, wz);

    const float sx = source[3 * idx], sy = source[3 * idx + 1], sz = source[3 * idx + 2];

    const float v[16] = { sx, sy, sz, wx, wy, wz,
                          sx * wx, sx * wy, sx * wz,
                          sy * wx, sy * wy, sy * wz,
                          sz * wx, sz * wy, sz * wz, 0.f };
    block_reduce16(v, b, blockIdx.x);
}

// ---------------------------------------------------------------------------
// Kabsch from accumulated sums. H formed in fp64 (cancellation-sensitive,
// cheap); eigensolve + R assembly in fp32 (4-cycle chain vs ~47-cycle DFMA).
// R = V diag(1,1,d) U^T with H = U S V^T, identical optimum to reference.
// ---------------------------------------------------------------------------
__device__ void kabsch_sums(const double* S, float* Rt) {
    const double invN = 1.0 / (double)NPTS;
    double cs[3] = { S[0] * invN, S[1] * invN, S[2] * invN };
    double ct[3] = { S[3] * invN, S[4] * invN, S[5] * invN };

    float H[3][3];
    for (int i = 0; i < 3; ++i)
        for (int j = 0; j < 3; ++j)
            H[i][j] = (float)(S[6 + 3 * i + j] - (double)NPTS * cs[i] * ct[j]);

    // A = H^T H (symmetric PSD), fp32
    float A[3][3];
    for (int i = 0; i < 3; ++i)
        for (int j = 0; j < 3; ++j)
            A[i][j] = H[0][i] * H[0][j] + H[1][i] * H[1][j] + H[2][i] * H[2][j];

    float V[3][3] = { {1,0,0},{0,1,0},{0,0,1} };
    const float diagmag = fabsf(A[0][0]) + fabsf(A[1][1]) + fabsf(A[2][2]);
    const float offeps  = diagmag * 1e-9f;
    for (int sweep = 0; sweep < 8; ++sweep) {
        const float off = fabsf(A[0][1]) + fabsf(A[0][2]) + fabsf(A[1][2]);
        if (off <= offeps) break;
        for (int pq = 0; pq < 3; ++pq) {
            const int p = (pq == 2) ? 1 : 0;
            const int q = (pq == 0) ? 1 : 2;
            const float apq = A[p][q];
            if (fabsf(apq) <= 0.0f) continue;
            const float theta = (A[q][q] - A[p][p]) / (2.0f * apq);
            const float tt = ((theta >= 0.0f) ? 1.0f : -1.0f) /
                             (fabsf(theta) + sqrtf(theta * theta + 1.0f));
            const float c = rsqrtf(tt * tt + 1.0f);
            const float s = tt * c;
            for (int k = 0; k < 3; ++k) { float a1 = A[p][k], a2 = A[q][k];
                A[p][k] = c * a1 - s * a2; A[q][k] = s * a1 + c * a2; }
            for (int k = 0; k < 3; ++k) { float a1 = A[k][p], a2 = A[k][q];
                A[k][p] = c * a1 - s * a2; A[k][q] = s * a1 + c * a2; }
            for (int k = 0; k < 3; ++k) { float v1 = V[k][p], v2 = V[k][q];
                V[k][p] = c * v1 - s * v2; V[k][q] = s * v1 + c * v2; }
        }
    }

    // sort eigenpairs descending
    int id[3] = { 0, 1, 2 };
    float w[3] = { A[0][0], A[1][1], A[2][2] };
    if (w[id[0]] < w[id[1]]) { int t0 = id[0]; id[0] = id[1]; id[1] = t0; }
    if (w[id[0]] < w[id[2]]) { int t0 = id[0]; id[0] = id[2]; id[2] = t0; }
    if (w[id[1]] < w[id[2]]) { int t0 = id[1]; id[1] = id[2]; id[2] = t0; }

    float v1[3], v2[3], v3[3];
    for (int k = 0; k < 3; ++k) { v1[k] = V[k][id[0]]; v2[k] = V[k][id[1]]; v3[k] = V[k][id[2]]; }

    float u1[3], u2[3], u3[3];
    for (int i = 0; i < 3; ++i) u1[i] = H[i][0] * v1[0] + H[i][1] * v1[1] + H[i][2] * v1[2];
    {
        float n1 = u1[0]*u1[0] + u1[1]*u1[1] + u1[2]*u1[2];
        float r = (n1 > 0.0f) ? rsqrtf(n1) : 0.0f;
        u1[0] *= r; u1[1] *= r; u1[2] *= r;
    }
    for (int i = 0; i < 3; ++i) u2[i] = H[i][0] * v2[0] + H[i][1] * v2[1] + H[i][2] * v2[2];
    {
        float pr = u1[0]*u2[0] + u1[1]*u2[1] + u1[2]*u2[2];
        u2[0] -= pr * u1[0]; u2[1] -= pr * u1[1]; u2[2] -= pr * u1[2];
        float n2 = u2[0]*u2[0] + u2[1]*u2[1] + u2[2]*u2[2];
        float r = (n2 > 0.0f) ? rsqrtf(n2) : 0.0f;
        u2[0] *= r; u2[1] *= r; u2[2] *= r;
    }
    u3[0] = u1[1]*u2[2] - u1[2]*u2[1];
    u3[1] = u1[2]*u2[0] - u1[0]*u2[2];
    u3[2] = u1[0]*u2[1] - u1[1]*u2[0];

    // d = det(V_sorted) (det(U)=+1 by construction)
    const float d =
        v1[0] * (v2[1]*v3[2] - v2[2]*v3[1]) -
        v1[1] * (v2[0]*v3[2] - v2[2]*v3[0]) +
        v1[2] * (v2[0]*v3[1] - v2[1]*v3[0]);

    float R[9];
    for (int i = 0; i < 3; ++i)
        for (int j = 0; j < 3; ++j)
            R[3 * i + j] = v1[i]*u1[j] + v2[i]*u2[j] + d * v3[i]*u3[j];
    for (int k = 0; k < 9; ++k) Rt[k] = R[k];
    for (int i = 0; i < 3; ++i)
        Rt[9 + i] = (float)ct[i] - (R[3*i]*(float)cs[0] + R[3*i+1]*(float)cs[1]
                                    + R[3*i+2]*(float)cs[2]);
}

// ---------------------------------------------------------------------------
// Finalize one ICP step: sum partials, kabsch, convergence, publish transform
// 1 block, 128 threads
// ---------------------------------------------------------------------------
__global__ void fin_kernel() {
    __shared__ double sums[BB][16];
    __shared__ float  Rsh[BB][12];
    __shared__ double errsh[BB];
    __shared__ int    convf[BB];
    __shared__ int    doneflag;

    const int tid = threadIdx.x;
    if (tid < BB * 16) {
        const int b = tid >> 4, q = tid & 15;
        double acc = 0.0;
        for (int blk = 0; blk < SBLK; ++blk) acc += (double)g_part[b][blk][q];
        sums[b][q] = acc;
    }
    __syncthreads();

    if (tid < BB) {
        const int b = tid;
        const double errnew = sums[b][15] / (double)NPTS;
        errsh[b] = errnew;
        convf[b] = (fabs(errnew - g_errlast[b]) < ICP_TOL) ? 1 : 0;
        kabsch_sums(sums[b], Rsh[b]);
    }
    __syncthreads();

    if (tid == 0) {
        const int all = convf[0] & convf[1] & convf[2] & convf[3];
        doneflag = g_done | all;
        g_done = doneflag;
    }
    __syncthreads();

    if (tid < BB) {
        const int b = tid;
        if (!doneflag) {
            g_errlast[b] = errsh[b];
            for (int k = 0; k < 12; ++k) g_Rt[b][k] = Rsh[b][k];
        } else {
            for (int k = 0; k < 12; ++k)
                g_Rt[b][k] = (k == 0 || k == 4 || k == 8) ? 1.f : 0.f;
        }
    }
}

// Final: kabsch(source, temporal_final) -> d_out [B,3,4]
__global__ void ffin_kernel(float* __restrict__ out) {
    __shared__ double sums[BB][16];
    __shared__ float  Rsh[BB][12];

    const int tid = threadIdx.x;
    if (tid < BB * 16) {
        const int b = tid >> 4, q = tid & 15;
        double acc = 0.0;
        for (int blk = 0; blk < SBLK; ++blk) acc += (double)g_part[b][blk][q];
        sums[b][q] = acc;
    }
    __syncthreads();
    if (tid < BB) kabsch_sums(sums[tid], Rsh[tid]);
    __syncthreads();

    if (tid < BB * 12) {
        const int b = tid / 12, k = tid % 12;
        const int i = k / 4, j = k % 4;   // map to [3][4] output layout
        float val;
        if (j < 3) val = Rsh[b][3 * i + j];
        else       val = Rsh[b][9 + i];
        out[b * 12 + i * 4 + j] = val;
    }
}

// ---------------------------------------------------------------------------
extern "C" void kernel_launch(void* const* d_in, const int* in_sizes, int n_in,
                              void* d_out, int out_size) {
    const float* source = (const float*)d_in[0];
    const float* target = (const float*)d_in[1];
    float*       out    = (float*)d_out;

    init_kernel<<<(BB * NPTS * 3 + 255) / 256, 256>>>(source);

    for (int k = 0; k < ICP_STEPS; ++k) {
        nn_kernel<<<dim3(SBLK, TSPLIT, BB), 256>>>(target);
        mom_kernel<<<dim3(SBLK, 1, BB), 256>>>(target);
        fin_kernel<<<1, 128>>>();
    }

    fmom_kernel<<<dim3(SBLK, 1, BB), 256>>>(source);
    ffin_kernel<<<1, 128>>>(out);
}